// round 6
// baseline (speedup 1.0000x reference)
#include <cuda_runtime.h>
#include <cstdint>
#include <math.h>

#define BB 2
#define NN 2048
#define DD 1024
#define HH 16
#define HD 64

// pre-split (hi,lo) float2 arrays
__device__ float2 g_x2[(size_t)BB*NN*DD];
__device__ float2 g_wq2[(size_t)DD*DD];
__device__ float2 g_wk2[(size_t)DD*DD];
__device__ float2 g_wv2[(size_t)DD*DD];
__device__ float2 g_wo2[(size_t)DD*DD];
__device__ float2 g_q2[(size_t)BB*HH*NN*HD];
__device__ float2 g_k2[(size_t)BB*HH*NN*HD];
__device__ float2 g_v2[(size_t)BB*HH*NN*HD];
__device__ float2 g_ctx2[(size_t)BB*NN*DD];
__device__ float  g_s[(size_t)512*262144];

__device__ __forceinline__ float tf32r(float x){
    uint32_t r; asm("cvt.rna.tf32.f32 %0, %1;" : "=r"(r) : "f"(x));
    return __uint_as_float(r);
}
__device__ __forceinline__ float2 tsplit(float x){
    float h = tf32r(x);
    return make_float2(h, tf32r(x - h));
}
__device__ __forceinline__ uint32_t smem_u32(const void* p){
    uint32_t a;
    asm("{ .reg .u64 t; cvta.to.shared.u64 t, %1; cvt.u32.u64 %0, t; }" : "=r"(a) : "l"(p));
    return a;
}
__device__ __forceinline__ void cpa16(uint32_t dst, const void* src){
    asm volatile("cp.async.cg.shared.global [%0], [%1], 16;" :: "r"(dst), "l"(src));
}
__device__ __forceinline__ void cpa_commit(){ asm volatile("cp.async.commit_group;" ::: "memory"); }
__device__ __forceinline__ void cpa_wait0(){ asm volatile("cp.async.wait_group 0;" ::: "memory"); }
__device__ __forceinline__ void cpa_wait1(){ asm volatile("cp.async.wait_group 1;" ::: "memory"); }

__device__ __forceinline__ void mma1(float4& d, uint32_t a0, uint32_t a1, uint32_t a2, uint32_t a3,
                                     uint32_t b0, uint32_t b1){
    asm volatile("mma.sync.aligned.m16n8k8.row.col.f32.tf32.tf32.f32 "
        "{%0,%1,%2,%3},{%4,%5,%6,%7},{%8,%9},{%0,%1,%2,%3};"
        : "+f"(d.x), "+f"(d.y), "+f"(d.z), "+f"(d.w)
        : "r"(a0), "r"(a1), "r"(a2), "r"(a3), "r"(b0), "r"(b1));
}
#define FU __float_as_uint
__device__ __forceinline__ void mma3(float4& d, const float2* a, const float2* b){
    mma1(d, FU(a[0].x), FU(a[1].x), FU(a[2].x), FU(a[3].x), FU(b[0].x), FU(b[1].x));
    mma1(d, FU(a[0].x), FU(a[1].x), FU(a[2].x), FU(a[3].x), FU(b[0].y), FU(b[1].y));
    mma1(d, FU(a[0].y), FU(a[1].y), FU(a[2].y), FU(a[3].y), FU(b[0].x), FU(b[1].x));
}

// ============================================================
// presplit: f32 -> (hi,lo) float2, 4 elems/thread
// ============================================================
__global__ __launch_bounds__(256) void presplit(const float4* __restrict__ src,
                                                float4* __restrict__ dst, int n4){
    int i = blockIdx.x * 256 + threadIdx.x;
    if (i < n4) {
        float4 v = src[i];
        float2 a = tsplit(v.x), b = tsplit(v.y), c = tsplit(v.z), d = tsplit(v.w);
        dst[2*i]   = make_float4(a.x, a.y, b.x, b.y);
        dst[2*i+1] = make_float4(c.x, c.y, d.x, d.y);
    }
}

// ============================================================
// GEMM core: 128x128 tile, BK=32, cp.async 2-stage.
// ============================================================
#define GST 36
#define GBUF (128*GST)   // float2 per operand buffer

__device__ __forceinline__ void g_issue(uint32_t sA, uint32_t sB,
        const float2* __restrict__ A2, const float2* __restrict__ B2,
        int m0, int n0, int k0, int tid){
#pragma unroll
    for (int i = 0; i < 8; i++) {
        int idx = tid + i * 256;        // 2048 chunks, 16/row
        int r = idx >> 4, c = (idx & 15) * 2;
        uint32_t off = (uint32_t)(r * GST + c) * 8u;
        cpa16(sA + off, A2 + (size_t)(m0 + r) * DD + k0 + c);
        cpa16(sB + off, B2 + (size_t)(n0 + r) * DD + k0 + c);
    }
}
__device__ __forceinline__ void g_mma(const float2* As, const float2* Bs, float4 (&acc)[2][8],
                                      int wm, int wn, int g, int t){
#pragma unroll
    for (int kk = 0; kk < 4; kk++) {
        float2 af[2][4];
#pragma unroll
        for (int mt = 0; mt < 2; mt++) {
            int rb = wm * 32 + mt * 16;
            af[mt][0] = As[(rb + g)     * GST + kk * 8 + t];
            af[mt][1] = As[(rb + g + 8) * GST + kk * 8 + t];
            af[mt][2] = As[(rb + g)     * GST + kk * 8 + t + 4];
            af[mt][3] = As[(rb + g + 8) * GST + kk * 8 + t + 4];
        }
#pragma unroll
        for (int nt = 0; nt < 8; nt++) {
            int nr = wn * 64 + nt * 8 + g;
            float2 bf[2];
            bf[0] = Bs[nr * GST + kk * 8 + t];
            bf[1] = Bs[nr * GST + kk * 8 + t + 4];
            mma3(acc[0][nt], af[0], bf);
            mma3(acc[1][nt], af[1], bf);
        }
    }
}
__device__ __forceinline__ void g_run(const float2* __restrict__ A2, const float2* __restrict__ B2,
                                      float2* sm, int m0, int n0, int tid,
                                      float4 (&acc)[2][8], int wm, int wn, int g, int t){
    uint32_t sb = smem_u32(sm);
    g_issue(sb, sb + GBUF * 8u, A2, B2, m0, n0, 0, tid);
    cpa_commit();
    for (int k0 = 0; k0 < DD; k0 += 32) {
        int cur = (k0 >> 5) & 1;
        if (k0 + 32 < DD) {
            int nxt = cur ^ 1;
            g_issue(sb + (uint32_t)nxt * (2u*GBUF*8u), sb + (uint32_t)nxt * (2u*GBUF*8u) + GBUF*8u,
                    A2, B2, m0, n0, k0 + 32, tid);
            cpa_commit();
            cpa_wait1();
        } else {
            cpa_wait0();
        }
        __syncthreads();
        const float2* As = sm + cur * (2*GBUF);
        const float2* Bs = As + GBUF;
        g_mma(As, Bs, acc, wm, wn, g, t);
        __syncthreads();
    }
}

// fused QKV, epilogue writes pre-split q/k/v
__global__ __launch_bounds__(256) void gemm_qkv(void)
{
    extern __shared__ float2 gsm[];
    const int tid = threadIdx.x, lane = tid & 31, wid = tid >> 5;
    const int g = lane >> 2, t = lane & 3;
    const int wm = wid >> 1, wn = wid & 1;
    const int mat = blockIdx.x >> 3;
    const int m0 = blockIdx.y * 128, n0 = (blockIdx.x & 7) * 128;
    const float2* W2 = (mat == 0) ? g_wq2 : (mat == 1) ? g_wk2 : g_wv2;
    float2* C2 = (mat == 0) ? g_q2 : (mat == 1) ? g_k2 : g_v2;

    float4 acc[2][8];
#pragma unroll
    for (int i = 0; i < 2; i++)
#pragma unroll
        for (int j = 0; j < 8; j++) acc[i][j] = make_float4(0.f, 0.f, 0.f, 0.f);

    g_run(g_x2, W2, gsm, m0, n0, tid, acc, wm, wn, g, t);

#pragma unroll
    for (int mt = 0; mt < 2; mt++) {
        int r0 = m0 + wm * 32 + mt * 16 + g;
#pragma unroll
        for (int nt = 0; nt < 8; nt++) {
            int n = n0 + wn * 64 + nt * 8 + 2 * t;
            int h = n >> 6, cc = n & 63;
            float4 c = acc[mt][nt];
            int b0r = r0 >> 11, i0r = r0 & (NN - 1);
            int b1r = (r0 + 8) >> 11, i1r = (r0 + 8) & (NN - 1);
            float2 sx = tsplit(c.x), sy = tsplit(c.y), sz = tsplit(c.z), sw = tsplit(c.w);
            *(float4*)&C2[((size_t)(b0r * HH + h) * NN + i0r) * HD + cc] = make_float4(sx.x, sx.y, sy.x, sy.y);
            *(float4*)&C2[((size_t)(b1r * HH + h) * NN + i1r) * HD + cc] = make_float4(sz.x, sz.y, sw.x, sw.y);
        }
    }
}

__global__ __launch_bounds__(256) void gemm_out(const float* __restrict__ bias, float* __restrict__ C)
{
    extern __shared__ float2 gsm[];
    const int tid = threadIdx.x, lane = tid & 31, wid = tid >> 5;
    const int g = lane >> 2, t = lane & 3;
    const int wm = wid >> 1, wn = wid & 1;
    const int m0 = blockIdx.y * 128, n0 = blockIdx.x * 128;

    float4 acc[2][8];
#pragma unroll
    for (int i = 0; i < 2; i++)
#pragma unroll
        for (int j = 0; j < 8; j++) acc[i][j] = make_float4(0.f, 0.f, 0.f, 0.f);

    g_run(g_ctx2, g_wo2, gsm, m0, n0, tid, acc, wm, wn, g, t);

#pragma unroll
    for (int mt = 0; mt < 2; mt++) {
        int r0 = m0 + wm * 32 + mt * 16 + g;
#pragma unroll
        for (int nt = 0; nt < 8; nt++) {
            int n = n0 + wn * 64 + nt * 8 + 2 * t;
            float bx = bias[n], by = bias[n + 1];
            float4 c = acc[mt][nt];
            *(float2*)&C[(size_t)r0 * DD + n]       = make_float2(c.x + bx, c.y + by);
            *(float2*)&C[(size_t)(r0 + 8) * DD + n] = make_float2(c.z + bx, c.w + by);
        }
    }
}

// ============================================================
// Attention: 256 thr, q-tile 128, key-tile 64, S in gmem cache.
// ============================================================
#define AST 68

__device__ __forceinline__ void a_issue64(uint32_t dstBase, const float2* __restrict__ src,
                                          int row0, int tid){
#pragma unroll
    for (int i = 0; i < 8; i++) {
        int idx = tid + i * 256;       // 2048 chunks, 32/row
        int r = idx >> 5, c = (idx & 31) * 2;
        cpa16(dstBase + (uint32_t)(r * AST + c) * 8u, src + (size_t)(row0 + r) * HD + c);
    }
}

__global__ __launch_bounds__(256, 2) void attn_mma(void)
{
    extern __shared__ float2 asm_[];
    float2* Qs = asm_;                 // pass A
    float2* Ks = asm_ + 128 * AST;
    float2* Ps = asm_;                 // pass B aliases
    float2* Vs = asm_ + 128 * AST;
    uint32_t sbQ = smem_u32(asm_);
    uint32_t sbK = sbQ + 128u * AST * 8u;

    const int tid = threadIdx.x, lane = tid & 31, wid = tid >> 5;
    const int g = lane >> 2, t = lane & 3;
    const int qt = 15 - blockIdx.x;
    const int h = blockIdx.y, b = blockIdx.z;
    const int q0 = qt * 128, ktmax = 2 * qt + 1;
    const size_t ho = (size_t)(b * HH + h) * NN * HD;
    const float2 *Q2 = g_q2 + ho, *K2 = g_k2 + ho, *V2 = g_v2 + ho;
    float* Sc = g_s + (size_t)((b * HH + h) * 16 + qt) * 262144 + wid * 1024 + lane * 2;

    const int wr = wid * 16;
    const int gr0 = q0 + wr + g, gr1 = gr0 + 8;

    // Q tile: 4096 chunks
#pragma unroll
    for (int i = 0; i < 16; i++) {
        int idx = tid + i * 256;
        int r = idx >> 5, c = (idx & 31) * 2;
        cpa16(sbQ + (uint32_t)(r * AST + c) * 8u, Q2 + (size_t)(q0 + r) * HD + c);
    }
    a_issue64(sbK, K2, 0, tid);
    cpa_commit();
    cpa_wait0();
    __syncthreads();

    float mr[2] = {-1e30f, -1e30f}, lr[2] = {0.f, 0.f}, tr[2] = {0.f, 0.f};

    // ================= pass A =================
    for (int kt = 0; kt <= ktmax; kt++) {
        int ktb = kt * 64;
        bool act = (ktb <= q0 + wr + 15);
        float4 s[8];
        if (act) {
#pragma unroll
            for (int nt = 0; nt < 8; nt++) s[nt] = make_float4(0.f, 0.f, 0.f, 0.f);
#pragma unroll
            for (int kk = 0; kk < 8; kk++) {
                float2 af[4];
                af[0] = Qs[(wr + g)     * AST + kk * 8 + t];
                af[1] = Qs[(wr + g + 8) * AST + kk * 8 + t];
                af[2] = Qs[(wr + g)     * AST + kk * 8 + t + 4];
                af[3] = Qs[(wr + g + 8) * AST + kk * 8 + t + 4];
#pragma unroll
                for (int nt = 0; nt < 8; nt++) {
                    float2 bf[2];
                    bf[0] = Ks[(nt * 8 + g) * AST + kk * 8 + t];
                    bf[1] = Ks[(nt * 8 + g) * AST + kk * 8 + t + 4];
                    mma3(s[nt], af, bf);
                }
            }
        }
        __syncthreads();                       // all warps done reading Ks
        if (kt < ktmax) { a_issue64(sbK, K2, ktb + 64, tid); cpa_commit(); }
        if (act) {
            float* sp = Sc + kt * 8192;
#pragma unroll
            for (int rr = 0; rr < 2; rr++) {
                int gr = rr ? gr1 : gr0;
                float sv[16], cm = -1e30f;
#pragma unroll
                for (int nt = 0; nt < 8; nt++) {
                    float x0 = rr ? s[nt].z : s[nt].x;
                    float x1 = rr ? s[nt].w : s[nt].y;
                    int gc = ktb + nt * 8 + 2 * t;
                    sv[2*nt]   = (gc     <= gr) ? x0 * 0.125f : -1e30f;
                    sv[2*nt+1] = (gc + 1 <= gr) ? x1 * 0.125f : -1e30f;
                    cm = fmaxf(cm, fmaxf(sv[2*nt], sv[2*nt+1]));
                    *(float2*)&sp[(rr * 8 + nt) * 64] = make_float2(sv[2*nt], sv[2*nt+1]);
                }
                cm = fmaxf(cm, __shfl_xor_sync(0xffffffffu, cm, 1));
                cm = fmaxf(cm, __shfl_xor_sync(0xffffffffu, cm, 2));
                if (cm > -1e29f) {
                    float mn = fmaxf(mr[rr], cm), se = 0.f, st = 0.f;
#pragma unroll
                    for (int i = 0; i < 16; i++) {
                        float e = __expf(sv[i] - mn);
                        se += e; st = fmaf(e, sv[i], st);
                    }
                    se += __shfl_xor_sync(0xffffffffu, se, 1);
                    se += __shfl_xor_sync(0xffffffffu, se, 2);
                    st += __shfl_xor_sync(0xffffffffu, st, 1);
                    st += __shfl_xor_sync(0xffffffffu, st, 2);
                    float corr = __expf(mr[rr] - mn);
                    lr[rr] = fmaf(lr[rr], corr, se);
                    tr[rr] = fmaf(tr[rr], corr, st);
                    mr[rr] = mn;
                }
            }
        }
        if (kt < ktmax) { cpa_wait0(); __syncthreads(); }
    }

    float bs[2], bm[2], l2[2] = {0.f, 0.f};
#pragma unroll
    for (int rr = 0; rr < 2; rr++) {
        float ent = logf(lr[rr]) + mr[rr] - tr[rr] / lr[rr];
        float beta = 1.f;
        if (ent > 0.5f) {
            float poly = ((((-0.037f * ent + 0.481f) * ent - 2.3f) * ent + 4.917f) * ent - 1.791f);
            beta = fmaxf(poly, 1.f);
        }
        bs[rr] = beta;
        bm[rr] = beta * mr[rr];
    }

    float4 o[8];
#pragma unroll
    for (int nt = 0; nt < 8; nt++) o[nt] = make_float4(0.f, 0.f, 0.f, 0.f);

    __syncthreads();                            // Ks/Qs -> Vs/Ps alias safety
    a_issue64(sbK, V2, 0, tid);                 // V tile kt=0 (Vs == Ks region)
    cpa_commit();

    // ================= pass B =================
    for (int kt = 0; kt <= ktmax; kt++) {
        int ktb = kt * 64;
        bool act = (ktb <= q0 + wr + 15);
        if (act) {
            const float* sp = Sc + kt * 8192;
#pragma unroll
            for (int rr = 0; rr < 2; rr++) {
                int prow = wr + g + rr * 8;
#pragma unroll
                for (int nt = 0; nt < 8; nt++) {
                    float2 sv2 = *(const float2*)&sp[(rr * 8 + nt) * 64];
                    float p0 = __expf(fmaf(bs[rr], sv2.x, -bm[rr]));
                    float p1 = __expf(fmaf(bs[rr], sv2.y, -bm[rr]));
                    l2[rr] += p0 + p1;
                    float2 s0 = tsplit(p0), s1 = tsplit(p1);
                    *(float4*)&Ps[prow * AST + nt * 8 + 2 * t] = make_float4(s0.x, s0.y, s1.x, s1.y);
                }
            }
        }
        cpa_wait0();
        __syncthreads();                        // V ready + Ps visible
        if (act) {
#pragma unroll
            for (int kk = 0; kk < 8; kk++) {
                float2 af[4];
                af[0] = Ps[(wr + g)     * AST + kk * 8 + t];
                af[1] = Ps[(wr + g + 8) * AST + kk * 8 + t];
                af[2] = Ps[(wr + g)     * AST + kk * 8 + t + 4];
                af[3] = Ps[(wr + g + 8) * AST + kk * 8 + t + 4];
#pragma unroll
                for (int nt = 0; nt < 8; nt++) {
                    float2 bf[2];
                    bf[0] = Vs[(kk * 8 + t)     * AST + nt * 8 + g];
                    bf[1] = Vs[(kk * 8 + t + 4) * AST + nt * 8 + g];
                    mma3(o[nt], af, bf);
                }
            }
        }
        __syncthreads();                        // done reading Vs
        if (kt < ktmax) { a_issue64(sbK, V2, ktb + 64, tid); cpa_commit(); }
    }

#pragma unroll
    for (int rr = 0; rr < 2; rr++) {
        l2[rr] += __shfl_xor_sync(0xffffffffu, l2[rr], 1);
        l2[rr] += __shfl_xor_sync(0xffffffffu, l2[rr], 2);
    }
    float inv0 = 1.f / l2[0], inv1 = 1.f / l2[1];
    size_t row0 = ((size_t)(b * NN) + gr0) * DD + h * HD;
    size_t row1 = ((size_t)(b * NN) + gr1) * DD + h * HD;
#pragma unroll
    for (int nt = 0; nt < 8; nt++) {
        int c = nt * 8 + 2 * t;
        float2 a0 = tsplit(o[nt].x * inv0), a1 = tsplit(o[nt].y * inv0);
        float2 c0 = tsplit(o[nt].z * inv1), c1 = tsplit(o[nt].w * inv1);
        *(float4*)&g_ctx2[row0 + c] = make_float4(a0.x, a0.y, a1.x, a1.y);
        *(float4*)&g_ctx2[row1 + c] = make_float4(c0.x, c0.y, c1.x, c1.y);
    }
}

// ============================================================
extern "C" void kernel_launch(void* const* d_in, const int* in_sizes, int n_in,
                              void* d_out, int out_size)
{
    const float* x  = (const float*)d_in[0];
    const float* Wq = (const float*)d_in[1];
    const float* Wk = (const float*)d_in[2];
    const float* Wv = (const float*)d_in[3];
    const float* Wo = (const float*)d_in[4];
    const float* bo = (const float*)d_in[5];
    float* out = (float*)d_out;

    float2 *x2, *wq2, *wk2, *wv2, *wo2;
    cudaGetSymbolAddress((void**)&x2,  g_x2);
    cudaGetSymbolAddress((void**)&wq2, g_wq2);
    cudaGetSymbolAddress((void**)&wk2, g_wk2);
    cudaGetSymbolAddress((void**)&wv2, g_wv2);
    cudaGetSymbolAddress((void**)&wo2, g_wo2);

    const int gsmem = 4 * GBUF * (int)sizeof(float2);   // 147456
    const int asmem = 192 * AST * (int)sizeof(float2);  // 104448
    cudaFuncSetAttribute(gemm_qkv, cudaFuncAttributeMaxDynamicSharedMemorySize, gsmem);
    cudaFuncSetAttribute(gemm_out, cudaFuncAttributeMaxDynamicSharedMemorySize, gsmem);
    cudaFuncSetAttribute(attn_mma, cudaFuncAttributeMaxDynamicSharedMemorySize, asmem);

    presplit<<<4096, 256>>>((const float4*)x,  (float4*)x2,  (BB*NN*DD)/4);
    presplit<<<1024, 256>>>((const float4*)Wq, (float4*)wq2, (DD*DD)/4);
    presplit<<<1024, 256>>>((const float4*)Wk, (float4*)wk2, (DD*DD)/4);
    presplit<<<1024, 256>>>((const float4*)Wv, (float4*)wv2, (DD*DD)/4);
    presplit<<<1024, 256>>>((const float4*)Wo, (float4*)wo2, (DD*DD)/4);

    dim3 qg(24, 32);
    gemm_qkv<<<qg, 256, gsmem>>>();

    dim3 ag(NN / 128, HH, BB);
    attn_mma<<<ag, 256, asmem>>>();

    dim3 og(8, 32);
    gemm_out<<<og, 256, gsmem>>>(bo, out);
}

// round 7
// speedup vs baseline: 2.3848x; 2.3848x over previous
#include <cuda_runtime.h>
#include <cstdint>

#define BB 2
#define NN 2048
#define DD 1024
#define HH 16
#define HD 64
typedef unsigned short u16;
typedef uint32_t u32;

// bf16 hi/lo planes
__device__ __align__(16) u16 g_xh[(size_t)BB*NN*DD];
__device__ __align__(16) u16 g_xl[(size_t)BB*NN*DD];
__device__ __align__(16) u16 g_wh[4][(size_t)DD*DD];   // q,k,v,o
__device__ __align__(16) u16 g_wl[4][(size_t)DD*DD];
__device__ __align__(16) u16 g_qh[(size_t)BB*HH*NN*HD];
__device__ __align__(16) u16 g_ql[(size_t)BB*HH*NN*HD];
__device__ __align__(16) u16 g_kh[(size_t)BB*HH*NN*HD];
__device__ __align__(16) u16 g_kl[(size_t)BB*HH*NN*HD];
__device__ __align__(16) u16 g_vh[(size_t)BB*HH*NN*HD];
__device__ __align__(16) u16 g_vl[(size_t)BB*HH*NN*HD];
__device__ __align__(16) u16 g_cth[(size_t)BB*NN*DD];
__device__ __align__(16) u16 g_ctl[(size_t)BB*NN*DD];
__device__ float g_s[(size_t)512*262144];

__device__ __forceinline__ void bsplit(float x, u16 &h, u16 &l){
    asm("cvt.rn.bf16.f32 %0, %1;" : "=h"(h) : "f"(x));
    float hf = __uint_as_float((u32)h << 16);
    asm("cvt.rn.bf16.f32 %0, %1;" : "=h"(l) : "f"(x - hf));
}
__device__ __forceinline__ u32 smem_u32(const void* p){
    u32 a;
    asm("{ .reg .u64 t; cvta.to.shared.u64 t, %1; cvt.u32.u64 %0, t; }" : "=r"(a) : "l"(p));
    return a;
}
__device__ __forceinline__ void cpa16(u32 dst, const void* src){
    asm volatile("cp.async.cg.shared.global [%0], [%1], 16;" :: "r"(dst), "l"(src));
}
__device__ __forceinline__ void cpa_commit(){ asm volatile("cp.async.commit_group;" ::: "memory"); }
__device__ __forceinline__ void cpa_wait0(){ asm volatile("cp.async.wait_group 0;" ::: "memory"); }
__device__ __forceinline__ void cpa_wait1(){ asm volatile("cp.async.wait_group 1;" ::: "memory"); }

__device__ __forceinline__ void ldmx4(u32* r, u32 a){
    asm volatile("ldmatrix.sync.aligned.m8n8.x4.shared.b16 {%0,%1,%2,%3}, [%4];"
        : "=r"(r[0]), "=r"(r[1]), "=r"(r[2]), "=r"(r[3]) : "r"(a));
}
__device__ __forceinline__ void ldmx4t(u32* r, u32 a){
    asm volatile("ldmatrix.sync.aligned.m8n8.x4.trans.shared.b16 {%0,%1,%2,%3}, [%4];"
        : "=r"(r[0]), "=r"(r[1]), "=r"(r[2]), "=r"(r[3]) : "r"(a));
}
__device__ __forceinline__ void mmab(float4& d, const u32* a, u32 b0, u32 b1){
    asm volatile("mma.sync.aligned.m16n8k16.row.col.f32.bf16.bf16.f32 "
        "{%0,%1,%2,%3},{%4,%5,%6,%7},{%8,%9},{%0,%1,%2,%3};"
        : "+f"(d.x), "+f"(d.y), "+f"(d.z), "+f"(d.w)
        : "r"(a[0]), "r"(a[1]), "r"(a[2]), "r"(a[3]), "r"(b0), "r"(b1));
}
__device__ __forceinline__ void mma3b(float4& d, const u32* ah, const u32* al,
                                      const u32* bh, const u32* bl, int ng){
    mmab(d, ah, bh[2*ng], bh[2*ng+1]);
    mmab(d, ah, bl[2*ng], bl[2*ng+1]);
    mmab(d, al, bh[2*ng], bh[2*ng+1]);
}

// ============================================================
// presplit: f32 -> bf16 hi/lo planes
// ============================================================
__global__ __launch_bounds__(256) void presplit(const float4* __restrict__ src,
                                                ushort4* __restrict__ hi,
                                                ushort4* __restrict__ lo, int n4){
    int i = blockIdx.x * 256 + threadIdx.x;
    if (i >= n4) return;
    float4 v = src[i];
    u16 h0,l0,h1,l1,h2,l2,h3,l3;
    bsplit(v.x,h0,l0); bsplit(v.y,h1,l1); bsplit(v.z,h2,l2); bsplit(v.w,h3,l3);
    hi[i] = make_ushort4(h0,h1,h2,h3);
    lo[i] = make_ushort4(l0,l1,l2,l3);
}

// ============================================================
// GEMM core: 128x128 tile, BK=32, 2-stage cp.async, bf16 planes.
// rows padded: 32 bf16 = 64B data, stride 80B.
// ============================================================
#define GRS 80
#define GPL 10240
#define GSTG 40960

__device__ __forceinline__ void g_issue(u32 sb_stage,
        const u16* __restrict__ Ah, const u16* __restrict__ Al,
        const u16* __restrict__ Bh, const u16* __restrict__ Bl,
        int m0, int n0, int k0, int tid){
#pragma unroll
    for (int i = 0; i < 8; i++) {
        int p = i >> 1;
        int rem = tid + (i & 1) * 256;
        int r = rem >> 2, c = rem & 3;
        u32 sa = sb_stage + (u32)p * GPL + (u32)(r * GRS + c * 16);
        const u16* g = (p == 0) ? Ah : (p == 1) ? Al : (p == 2) ? Bh : Bl;
        int rb = (p < 2) ? m0 : n0;
        cpa16(sa, g + (size_t)(rb + r) * DD + k0 + c * 8);
    }
}

__device__ __forceinline__ void g_run(const u16* Ah, const u16* Al, const u16* Bh, const u16* Bl,
                                      char* sm, int m0, int n0, int tid,
                                      float4 (&acc)[2][8], int wm, int wn, int lane){
    u32 sb = smem_u32(sm);
    u32 aBase = sb + (u32)((wm * 32 + (lane & 7) + 8 * ((lane >> 3) & 1)) * GRS + 16 * (lane >> 4));
    u32 bBase = sb + 20480u + (u32)((wn * 64 + (lane & 7) + 8 * ((lane >> 4) & 1)) * GRS + 16 * ((lane >> 3) & 1));

    g_issue(sb, Ah, Al, Bh, Bl, m0, n0, 0, tid);
    cpa_commit();
    for (int k0 = 0; k0 < DD; k0 += 32) {
        u32 so = ((k0 >> 5) & 1) ? GSTG : 0u;
        if (k0 + 32 < DD) {
            u32 sn = so ^ GSTG;
            g_issue(sb + sn, Ah, Al, Bh, Bl, m0, n0, k0 + 32, tid);
            cpa_commit();
            cpa_wait1();
        } else {
            cpa_wait0();
        }
        __syncthreads();
#pragma unroll
        for (int kk = 0; kk < 2; kk++) {
            u32 ah4[2][4], al4[2][4];
#pragma unroll
            for (int mt = 0; mt < 2; mt++) {
                ldmx4(ah4[mt], aBase + so + (u32)(mt * 1280 + kk * 32));
                ldmx4(al4[mt], aBase + so + GPL + (u32)(mt * 1280 + kk * 32));
            }
#pragma unroll
            for (int ntp = 0; ntp < 4; ntp++) {
                u32 bh4[4], bl4[4];
                ldmx4(bh4, bBase + so + (u32)(ntp * 1280 + kk * 32));
                ldmx4(bl4, bBase + so + GPL + (u32)(ntp * 1280 + kk * 32));
#pragma unroll
                for (int mt = 0; mt < 2; mt++) {
                    mma3b(acc[mt][ntp*2+0], ah4[mt], al4[mt], bh4, bl4, 0);
                    mma3b(acc[mt][ntp*2+1], ah4[mt], al4[mt], bh4, bl4, 1);
                }
            }
        }
        __syncthreads();
    }
}

__global__ __launch_bounds__(256, 2) void gemm_qkv(void)
{
    extern __shared__ char gsm[];
    const int tid = threadIdx.x, lane = tid & 31, wid = tid >> 5;
    const int g = lane >> 2, t = lane & 3;
    const int wm = wid >> 1, wn = wid & 1;
    const int mat = blockIdx.x >> 3;
    const int m0 = blockIdx.y * 128, n0 = (blockIdx.x & 7) * 128;
    const u16 *Bh = g_wh[mat], *Bl = g_wl[mat];
    u16 *Ch, *Cl;
    if (mat == 0) { Ch = g_qh; Cl = g_ql; }
    else if (mat == 1) { Ch = g_kh; Cl = g_kl; }
    else { Ch = g_vh; Cl = g_vl; }

    float4 acc[2][8];
#pragma unroll
    for (int i = 0; i < 2; i++)
#pragma unroll
        for (int j = 0; j < 8; j++) acc[i][j] = make_float4(0.f,0.f,0.f,0.f);

    g_run(g_xh, g_xl, Bh, Bl, gsm, m0, n0, tid, acc, wm, wn, lane);

#pragma unroll
    for (int mt = 0; mt < 2; mt++) {
        int r0 = m0 + wm * 32 + mt * 16 + g;
#pragma unroll
        for (int nt = 0; nt < 8; nt++) {
            int n = n0 + wn * 64 + nt * 8 + 2 * t;
            int h = n >> 6, cc = n & 63;
            float4 c = acc[mt][nt];
            int b0r = r0 >> 11, i0r = r0 & (NN - 1);
            int b1r = (r0 + 8) >> 11, i1r = (r0 + 8) & (NN - 1);
            size_t i0 = ((size_t)(b0r * HH + h) * NN + i0r) * HD + cc;
            size_t i1 = ((size_t)(b1r * HH + h) * NN + i1r) * HD + cc;
            u16 h0,l0,h1,l1;
            bsplit(c.x,h0,l0); bsplit(c.y,h1,l1);
            *(ushort2*)&Ch[i0] = make_ushort2(h0,h1);
            *(ushort2*)&Cl[i0] = make_ushort2(l0,l1);
            bsplit(c.z,h0,l0); bsplit(c.w,h1,l1);
            *(ushort2*)&Ch[i1] = make_ushort2(h0,h1);
            *(ushort2*)&Cl[i1] = make_ushort2(l0,l1);
        }
    }
}

__global__ __launch_bounds__(256, 2) void gemm_out(const float* __restrict__ bias,
                                                   float* __restrict__ C)
{
    extern __shared__ char gsm[];
    const int tid = threadIdx.x, lane = tid & 31, wid = tid >> 5;
    const int g = lane >> 2, t = lane & 3;
    const int wm = wid >> 1, wn = wid & 1;
    const int m0 = blockIdx.y * 128, n0 = blockIdx.x * 128;

    float4 acc[2][8];
#pragma unroll
    for (int i = 0; i < 2; i++)
#pragma unroll
        for (int j = 0; j < 8; j++) acc[i][j] = make_float4(0.f,0.f,0.f,0.f);

    g_run(g_cth, g_ctl, g_wh[3], g_wl[3], gsm, m0, n0, tid, acc, wm, wn, lane);

#pragma unroll
    for (int mt = 0; mt < 2; mt++) {
        int r0 = m0 + wm * 32 + mt * 16 + g;
#pragma unroll
        for (int nt = 0; nt < 8; nt++) {
            int n = n0 + wn * 64 + nt * 8 + 2 * t;
            float bx = bias[n], by = bias[n + 1];
            float4 c = acc[mt][nt];
            *(float2*)&C[(size_t)r0 * DD + n]       = make_float2(c.x + bx, c.y + by);
            *(float2*)&C[(size_t)(r0 + 8) * DD + n] = make_float2(c.z + bx, c.w + by);
        }
    }
}

// ============================================================
// Attention: 256 thr, q-tile 128, key-tile 64, bf16 planes.
// rows: 64 bf16 = 128B data, stride 144B.
// ============================================================
#define ARS 144
#define AQPL 18432u   // 128*144
#define AKPL 9216u    // 64*144
#define AK_OFF 36864u
#define ASMEM 55296

__device__ __forceinline__ void a_issueKV(u32 sb, const u16* __restrict__ gh,
                                          const u16* __restrict__ gl, int row0, int tid){
#pragma unroll
    for (int i = 0; i < 4; i++) {
        int p = i >> 1;
        int rem = tid + (i & 1) * 256;
        int r = rem >> 3, c = rem & 7;
        u32 sa = sb + AK_OFF + (u32)p * AKPL + (u32)(r * ARS + c * 16);
        const u16* g = p ? gl : gh;
        cpa16(sa, g + (size_t)(row0 + r) * HD + c * 8);
    }
}

__global__ __launch_bounds__(256, 2) void attn_mma(void)
{
    extern __shared__ char sm[];
    u32 sb = smem_u32(sm);

    const int tid = threadIdx.x, lane = tid & 31, wid = tid >> 5;
    const int g = lane >> 2, t = lane & 3;
    const int qt = 15 - blockIdx.x;
    const int h = blockIdx.y, b = blockIdx.z;
    const int q0 = qt * 128, ktmax = 2 * qt + 1;
    const size_t ho = (size_t)(b * HH + h) * NN * HD;
    const u16 *Qh = g_qh + ho, *Ql = g_ql + ho;
    const u16 *Kh = g_kh + ho, *Kl = g_kl + ho;
    const u16 *Vh = g_vh + ho, *Vl = g_vl + ho;
    float* Sc = g_s + (size_t)((b * HH + h) * 16 + qt) * 262144 + wid * 1024 + lane * 2;

    const int wr = wid * 16;
    const int gr0 = q0 + wr + g, gr1 = gr0 + 8;

    const u32 qBase = sb + (u32)((wr + (lane & 7) + 8 * ((lane >> 3) & 1)) * ARS + 16 * (lane >> 4));
    const u32 kBase = sb + AK_OFF + (u32)(((lane & 7) + 8 * ((lane >> 4) & 1)) * ARS + 16 * ((lane >> 3) & 1));
    const u32 vBase = sb + AK_OFF + (u32)(((lane & 7) + 8 * ((lane >> 3) & 1)) * ARS + 16 * (lane >> 4));

    // Q tile (2048 chunks) + K tile 0
#pragma unroll
    for (int i = 0; i < 8; i++) {
        int p = i >> 2;
        int rem = tid + (i & 3) * 256;
        int r = rem >> 3, c = rem & 7;
        u32 sa = sb + (u32)p * AQPL + (u32)(r * ARS + c * 16);
        const u16* gq = p ? Ql : Qh;
        cpa16(sa, gq + (size_t)(q0 + r) * HD + c * 8);
    }
    a_issueKV(sb, Kh, Kl, 0, tid);
    cpa_commit();
    cpa_wait0();
    __syncthreads();

    float mr[2] = {-1e30f, -1e30f}, lr[2] = {0.f, 0.f}, tr[2] = {0.f, 0.f};

    // ================= pass A =================
    for (int kt = 0; kt <= ktmax; kt++) {
        int ktb = kt * 64;
        bool act = (ktb <= q0 + wr + 15);
        float4 s[8];
        if (act) {
#pragma unroll
            for (int nt = 0; nt < 8; nt++) s[nt] = make_float4(0.f,0.f,0.f,0.f);
#pragma unroll
            for (int kk = 0; kk < 4; kk++) {
                u32 qh4[4], ql4[4];
                ldmx4(qh4, qBase + (u32)(kk * 32));
                ldmx4(ql4, qBase + AQPL + (u32)(kk * 32));
#pragma unroll
                for (int ntp = 0; ntp < 4; ntp++) {
                    u32 bh4[4], bl4[4];
                    ldmx4(bh4, kBase + (u32)(ntp * 2304 + kk * 32));
                    ldmx4(bl4, kBase + AKPL + (u32)(ntp * 2304 + kk * 32));
                    mma3b(s[ntp*2+0], qh4, ql4, bh4, bl4, 0);
                    mma3b(s[ntp*2+1], qh4, ql4, bh4, bl4, 1);
                }
            }
        }
        __syncthreads();
        if (kt < ktmax) { a_issueKV(sb, Kh, Kl, ktb + 64, tid); cpa_commit(); }
        if (act) {
            float* sp = Sc + kt * 8192;
#pragma unroll
            for (int rr = 0; rr < 2; rr++) {
                int gr = rr ? gr1 : gr0;
                float sv[16], cm = -1e30f;
#pragma unroll
                for (int nt = 0; nt < 8; nt++) {
                    float x0 = rr ? s[nt].z : s[nt].x;
                    float x1 = rr ? s[nt].w : s[nt].y;
                    int gc = ktb + nt * 8 + 2 * t;
                    sv[2*nt]   = (gc     <= gr) ? x0 * 0.125f : -1e30f;
                    sv[2*nt+1] = (gc + 1 <= gr) ? x1 * 0.125f : -1e30f;
                    cm = fmaxf(cm, fmaxf(sv[2*nt], sv[2*nt+1]));
                    *(float2*)&sp[(rr * 8 + nt) * 64] = make_float2(sv[2*nt], sv[2*nt+1]);
                }
                cm = fmaxf(cm, __shfl_xor_sync(0xffffffffu, cm, 1));
                cm = fmaxf(cm, __shfl_xor_sync(0xffffffffu, cm, 2));
                if (cm > -1e29f) {
                    float mn = fmaxf(mr[rr], cm), se = 0.f, st = 0.f;
#pragma unroll
                    for (int i = 0; i < 16; i++) {
                        float e = __expf(sv[i] - mn);
                        se += e; st = fmaf(e, sv[i], st);
                    }
                    se += __shfl_xor_sync(0xffffffffu, se, 1);
                    se += __shfl_xor_sync(0xffffffffu, se, 2);
                    st += __shfl_xor_sync(0xffffffffu, st, 1);
                    st += __shfl_xor_sync(0xffffffffu, st, 2);
                    float corr = __expf(mr[rr] - mn);
                    lr[rr] = fmaf(lr[rr], corr, se);
                    tr[rr] = fmaf(tr[rr], corr, st);
                    mr[rr] = mn;
                }
            }
        }
        if (kt < ktmax) { cpa_wait0(); __syncthreads(); }
    }

    float bsc[2], bm[2], l2[2] = {0.f, 0.f};
#pragma unroll
    for (int rr = 0; rr < 2; rr++) {
        float ent = logf(lr[rr]) + mr[rr] - tr[rr] / lr[rr];
        float beta = 1.f;
        if (ent > 0.5f) {
            float poly = ((((-0.037f * ent + 0.481f) * ent - 2.3f) * ent + 4.917f) * ent - 1.791f);
            beta = fmaxf(poly, 1.f);
        }
        bsc[rr] = beta;
        bm[rr] = beta * mr[rr];
    }

    float4 o[8];
#pragma unroll
    for (int nt = 0; nt < 8; nt++) o[nt] = make_float4(0.f,0.f,0.f,0.f);

    __syncthreads();
    a_issueKV(sb, Vh, Vl, 0, tid);
    cpa_commit();

    // ================= pass B =================
    for (int kt = 0; kt <= ktmax; kt++) {
        int ktb = kt * 64;
        bool act = (ktb <= q0 + wr + 15);
        if (act) {
            const float* sp = Sc + kt * 8192;
#pragma unroll
            for (int rr = 0; rr < 2; rr++) {
                int prow = wr + g + rr * 8;
#pragma unroll
                for (int nt = 0; nt < 8; nt++) {
                    float2 sv2 = *(const float2*)&sp[(rr * 8 + nt) * 64];
                    float p0 = __expf(fmaf(bsc[rr], sv2.x, -bm[rr]));
                    float p1 = __expf(fmaf(bsc[rr], sv2.y, -bm[rr]));
                    l2[rr] += p0 + p1;
                    u16 h0,l0h,h1,l1h;
                    bsplit(p0,h0,l0h); bsplit(p1,h1,l1h);
                    int boff = prow * ARS + (nt * 8 + 2 * t) * 2;
                    *(ushort2*)(sm + boff)          = make_ushort2(h0,h1);
                    *(ushort2*)(sm + AQPL + boff)   = make_ushort2(l0h,l1h);
                }
            }
        }
        cpa_wait0();
        __syncthreads();
        if (act) {
#pragma unroll
            for (int kk = 0; kk < 4; kk++) {
                u32 ph4[4], pl4[4];
                ldmx4(ph4, qBase + (u32)(kk * 32));
                ldmx4(pl4, qBase + AQPL + (u32)(kk * 32));
#pragma unroll
                for (int ntp = 0; ntp < 4; ntp++) {
                    u32 vh4[4], vl4[4];
                    ldmx4t(vh4, vBase + (u32)(kk * 2304 + ntp * 32));
                    ldmx4t(vl4, vBase + AKPL + (u32)(kk * 2304 + ntp * 32));
                    mma3b(o[ntp*2+0], ph4, pl4, vh4, vl4, 0);
                    mma3b(o[ntp*2+1], ph4, pl4, vh4, vl4, 1);
                }
            }
        }
        __syncthreads();
        if (kt < ktmax) { a_issueKV(sb, Vh, Vl, ktb + 64, tid); cpa_commit(); }
    }

#pragma unroll
    for (int rr = 0; rr < 2; rr++) {
        l2[rr] += __shfl_xor_sync(0xffffffffu, l2[rr], 1);
        l2[rr] += __shfl_xor_sync(0xffffffffu, l2[rr], 2);
    }
    float inv0 = 1.f / l2[0], inv1 = 1.f / l2[1];
    size_t row0 = ((size_t)(b * NN) + gr0) * DD + h * HD;
    size_t row1 = ((size_t)(b * NN) + gr1) * DD + h * HD;
#pragma unroll
    for (int nt = 0; nt < 8; nt++) {
        int c = nt * 8 + 2 * t;
        u16 h0,l0h,h1,l1h;
        bsplit(o[nt].x * inv0, h0, l0h); bsplit(o[nt].y * inv0, h1, l1h);
        *(ushort2*)&g_cth[row0 + c] = make_ushort2(h0,h1);
        *(ushort2*)&g_ctl[row0 + c] = make_ushort2(l0h,l1h);
        bsplit(o[nt].z * inv1, h0, l0h); bsplit(o[nt].w * inv1, h1, l1h);
        *(ushort2*)&g_cth[row1 + c] = make_ushort2(h0,h1);
        *(ushort2*)&g_ctl[row1 + c] = make_ushort2(l0h,l1h);
    }
}

// ============================================================
extern "C" void kernel_launch(void* const* d_in, const int* in_sizes, int n_in,
                              void* d_out, int out_size)
{
    const float* x  = (const float*)d_in[0];
    const float* Wq = (const float*)d_in[1];
    const float* Wk = (const float*)d_in[2];
    const float* Wv = (const float*)d_in[3];
    const float* Wo = (const float*)d_in[4];
    const float* bo = (const float*)d_in[5];
    float* out = (float*)d_out;

    u16 *xh, *xl, *wh, *wl;
    cudaGetSymbolAddress((void**)&xh, g_xh);
    cudaGetSymbolAddress((void**)&xl, g_xl);
    cudaGetSymbolAddress((void**)&wh, g_wh);
    cudaGetSymbolAddress((void**)&wl, g_wl);

    const int gsmem = 2 * GSTG;     // 81920
    cudaFuncSetAttribute(gemm_qkv, cudaFuncAttributeMaxDynamicSharedMemorySize, gsmem);
    cudaFuncSetAttribute(gemm_out, cudaFuncAttributeMaxDynamicSharedMemorySize, gsmem);
    cudaFuncSetAttribute(attn_mma, cudaFuncAttributeMaxDynamicSharedMemorySize, ASMEM);

    presplit<<<4096, 256>>>((const float4*)x, (ushort4*)xh, (ushort4*)xl, (BB*NN*DD)/4);
    const float* Ws[4] = {Wq, Wk, Wv, Wo};
    for (int m = 0; m < 4; m++)
        presplit<<<1024, 256>>>((const float4*)Ws[m],
                                (ushort4*)(wh + (size_t)m * DD * DD),
                                (ushort4*)(wl + (size_t)m * DD * DD), (DD*DD)/4);

    dim3 qg(24, 32);
    gemm_qkv<<<qg, 256, gsmem>>>();

    dim3 ag(NN / 128, HH, BB);
    attn_mma<<<ag, 256, ASMEM>>>();

    dim3 og(8, 32);
    gemm_out<<<og, 256, gsmem>>>(bo, out);
}

// round 8
// speedup vs baseline: 2.4767x; 1.0385x over previous
#include <cuda_runtime.h>
#include <cstdint>

#define BB 2
#define NN 2048
#define DD 1024
#define HH 16
#define HD 64
typedef unsigned short u16;
typedef uint32_t u32;

__device__ __align__(16) u16 g_xh[(size_t)BB*NN*DD];
__device__ __align__(16) u16 g_xl[(size_t)BB*NN*DD];
__device__ __align__(16) u16 g_wh[4][(size_t)DD*DD];
__device__ __align__(16) u16 g_wl[4][(size_t)DD*DD];
__device__ __align__(16) u16 g_qh[(size_t)BB*HH*NN*HD];
__device__ __align__(16) u16 g_ql[(size_t)BB*HH*NN*HD];
__device__ __align__(16) u16 g_kh[(size_t)BB*HH*NN*HD];
__device__ __align__(16) u16 g_kl[(size_t)BB*HH*NN*HD];
__device__ __align__(16) u16 g_vh[(size_t)BB*HH*NN*HD];
__device__ __align__(16) u16 g_vl[(size_t)BB*HH*NN*HD];
__device__ __align__(16) u16 g_cth[(size_t)BB*NN*DD];
__device__ __align__(16) u16 g_ctl[(size_t)BB*NN*DD];
__device__ float g_s[(size_t)512*262144];

__device__ __forceinline__ void bsplit(float x, u16 &h, u16 &l){
    asm("cvt.rn.bf16.f32 %0, %1;" : "=h"(h) : "f"(x));
    float hf = __uint_as_float((u32)h << 16);
    asm("cvt.rn.bf16.f32 %0, %1;" : "=h"(l) : "f"(x - hf));
}
__device__ __forceinline__ u32 packbf(float lo, float hi){
    u32 r; asm("cvt.rn.bf16x2.f32 %0, %1, %2;" : "=r"(r) : "f"(hi), "f"(lo));
    return r;
}
__device__ __forceinline__ u32 smem_u32(const void* p){
    u32 a;
    asm("{ .reg .u64 t; cvta.to.shared.u64 t, %1; cvt.u32.u64 %0, t; }" : "=r"(a) : "l"(p));
    return a;
}
__device__ __forceinline__ void cpa16(u32 dst, const void* src){
    asm volatile("cp.async.cg.shared.global [%0], [%1], 16;" :: "r"(dst), "l"(src));
}
__device__ __forceinline__ void cpa_commit(){ asm volatile("cp.async.commit_group;" ::: "memory"); }
__device__ __forceinline__ void cpa_wait0(){ asm volatile("cp.async.wait_group 0;" ::: "memory"); }
__device__ __forceinline__ void cpa_wait1(){ asm volatile("cp.async.wait_group 1;" ::: "memory"); }

__device__ __forceinline__ void ldmx4(u32* r, u32 a){
    asm volatile("ldmatrix.sync.aligned.m8n8.x4.shared.b16 {%0,%1,%2,%3}, [%4];"
        : "=r"(r[0]), "=r"(r[1]), "=r"(r[2]), "=r"(r[3]) : "r"(a));
}
__device__ __forceinline__ void ldmx4t(u32* r, u32 a){
    asm volatile("ldmatrix.sync.aligned.m8n8.x4.trans.shared.b16 {%0,%1,%2,%3}, [%4];"
        : "=r"(r[0]), "=r"(r[1]), "=r"(r[2]), "=r"(r[3]) : "r"(a));
}
__device__ __forceinline__ void mmab(float4& d, const u32* a, u32 b0, u32 b1){
    asm volatile("mma.sync.aligned.m16n8k16.row.col.f32.bf16.bf16.f32 "
        "{%0,%1,%2,%3},{%4,%5,%6,%7},{%8,%9},{%0,%1,%2,%3};"
        : "+f"(d.x), "+f"(d.y), "+f"(d.z), "+f"(d.w)
        : "r"(a[0]), "r"(a[1]), "r"(a[2]), "r"(a[3]), "r"(b0), "r"(b1));
}
__device__ __forceinline__ void mma3b(float4& d, const u32* ah, const u32* al,
                                      const u32* bh, const u32* bl, int ng){
    mmab(d, ah, bh[2*ng], bh[2*ng+1]);
    mmab(d, ah, bl[2*ng], bl[2*ng+1]);
    mmab(d, al, bh[2*ng], bh[2*ng+1]);
}

// ============================================================
// presplit: fused kernels
// ============================================================
__device__ __forceinline__ void dosplit4(const float4* src, ushort4* hi, ushort4* lo, int i){
    float4 v = src[i];
    u16 h0,l0,h1,l1,h2,l2,h3,l3;
    bsplit(v.x,h0,l0); bsplit(v.y,h1,l1); bsplit(v.z,h2,l2); bsplit(v.w,h3,l3);
    hi[i] = make_ushort4(h0,h1,h2,h3);
    lo[i] = make_ushort4(l0,l1,l2,l3);
}
__global__ __launch_bounds__(256) void presplitX(const float4* __restrict__ x){
    int i = blockIdx.x * 256 + threadIdx.x;
    dosplit4(x, (ushort4*)g_xh, (ushort4*)g_xl, i);
}
__global__ __launch_bounds__(256) void presplitW(const float4* __restrict__ Wq,
                                                 const float4* __restrict__ Wk,
                                                 const float4* __restrict__ Wv,
                                                 const float4* __restrict__ Wo){
    int m = blockIdx.y;
    const float4* src = (m == 0) ? Wq : (m == 1) ? Wk : (m == 2) ? Wv : Wo;
    int i = blockIdx.x * 256 + threadIdx.x;
    dosplit4(src, (ushort4*)g_wh[m], (ushort4*)g_wl[m], i);
}

// ============================================================
// GEMM core: 128x128 tile, BK=32, 2-stage cp.async, bf16 planes.
// ============================================================
#define GRS 80
#define GPL 10240
#define GSTG 40960

__device__ __forceinline__ void g_issue(u32 sb_stage,
        const u16* __restrict__ Ah, const u16* __restrict__ Al,
        const u16* __restrict__ Bh, const u16* __restrict__ Bl,
        int m0, int n0, int k0, int tid){
#pragma unroll
    for (int i = 0; i < 8; i++) {
        int p = i >> 1;
        int rem = tid + (i & 1) * 256;
        int r = rem >> 2, c = rem & 3;
        u32 sa = sb_stage + (u32)p * GPL + (u32)(r * GRS + c * 16);
        const u16* g = (p == 0) ? Ah : (p == 1) ? Al : (p == 2) ? Bh : Bl;
        int rb = (p < 2) ? m0 : n0;
        cpa16(sa, g + (size_t)(rb + r) * DD + k0 + c * 8);
    }
}

__device__ __forceinline__ void g_run(const u16* Ah, const u16* Al, const u16* Bh, const u16* Bl,
                                      char* sm, int m0, int n0, int tid,
                                      float4 (&acc)[2][8], int wm, int wn, int lane){
    u32 sb = smem_u32(sm);
    u32 aBase = sb + (u32)((wm * 32 + (lane & 7) + 8 * ((lane >> 3) & 1)) * GRS + 16 * (lane >> 4));
    u32 bBase = sb + 20480u + (u32)((wn * 64 + (lane & 7) + 8 * ((lane >> 4) & 1)) * GRS + 16 * ((lane >> 3) & 1));

    g_issue(sb, Ah, Al, Bh, Bl, m0, n0, 0, tid);
    cpa_commit();
    for (int k0 = 0; k0 < DD; k0 += 32) {
        u32 so = ((k0 >> 5) & 1) ? GSTG : 0u;
        if (k0 + 32 < DD) {
            u32 sn = so ^ GSTG;
            g_issue(sb + sn, Ah, Al, Bh, Bl, m0, n0, k0 + 32, tid);
            cpa_commit();
            cpa_wait1();
        } else {
            cpa_wait0();
        }
        __syncthreads();
#pragma unroll
        for (int kk = 0; kk < 2; kk++) {
            u32 ah4[2][4], al4[2][4];
#pragma unroll
            for (int mt = 0; mt < 2; mt++) {
                ldmx4(ah4[mt], aBase + so + (u32)(mt * 1280 + kk * 32));
                ldmx4(al4[mt], aBase + so + GPL + (u32)(mt * 1280 + kk * 32));
            }
#pragma unroll
            for (int ntp = 0; ntp < 4; ntp++) {
                u32 bh4[4], bl4[4];
                ldmx4(bh4, bBase + so + (u32)(ntp * 1280 + kk * 32));
                ldmx4(bl4, bBase + so + GPL + (u32)(ntp * 1280 + kk * 32));
#pragma unroll
                for (int mt = 0; mt < 2; mt++) {
                    mma3b(acc[mt][ntp*2+0], ah4[mt], al4[mt], bh4, bl4, 0);
                    mma3b(acc[mt][ntp*2+1], ah4[mt], al4[mt], bh4, bl4, 1);
                }
            }
        }
        __syncthreads();
    }
}

__global__ __launch_bounds__(256, 2) void gemm_qkv(void)
{
    extern __shared__ char gsm[];
    const int tid = threadIdx.x, lane = tid & 31, wid = tid >> 5;
    const int g = lane >> 2, t = lane & 3;
    const int wm = wid >> 1, wn = wid & 1;
    const int mat = blockIdx.x >> 3;
    const int m0 = blockIdx.y * 128, n0 = (blockIdx.x & 7) * 128;
    const u16 *Bh = g_wh[mat], *Bl = g_wl[mat];
    u16 *Ch, *Cl;
    if (mat == 0) { Ch = g_qh; Cl = g_ql; }
    else if (mat == 1) { Ch = g_kh; Cl = g_kl; }
    else { Ch = g_vh; Cl = g_vl; }

    float4 acc[2][8];
#pragma unroll
    for (int i = 0; i < 2; i++)
#pragma unroll
        for (int j = 0; j < 8; j++) acc[i][j] = make_float4(0.f,0.f,0.f,0.f);

    g_run(g_xh, g_xl, Bh, Bl, gsm, m0, n0, tid, acc, wm, wn, lane);

#pragma unroll
    for (int mt = 0; mt < 2; mt++) {
        int r0 = m0 + wm * 32 + mt * 16 + g;
#pragma unroll
        for (int nt = 0; nt < 8; nt++) {
            int n = n0 + wn * 64 + nt * 8 + 2 * t;
            int h = n >> 6, cc = n & 63;
            float4 c = acc[mt][nt];
            int b0r = r0 >> 11, i0r = r0 & (NN - 1);
            int b1r = (r0 + 8) >> 11, i1r = (r0 + 8) & (NN - 1);
            size_t i0 = ((size_t)(b0r * HH + h) * NN + i0r) * HD + cc;
            size_t i1 = ((size_t)(b1r * HH + h) * NN + i1r) * HD + cc;
            u16 h0,l0,h1,l1;
            bsplit(c.x,h0,l0); bsplit(c.y,h1,l1);
            *(ushort2*)&Ch[i0] = make_ushort2(h0,h1);
            *(ushort2*)&Cl[i0] = make_ushort2(l0,l1);
            bsplit(c.z,h0,l0); bsplit(c.w,h1,l1);
            *(ushort2*)&Ch[i1] = make_ushort2(h0,h1);
            *(ushort2*)&Cl[i1] = make_ushort2(l0,l1);
        }
    }
}

__global__ __launch_bounds__(256, 2) void gemm_out(const float* __restrict__ bias,
                                                   float* __restrict__ C)
{
    extern __shared__ char gsm[];
    const int tid = threadIdx.x, lane = tid & 31, wid = tid >> 5;
    const int g = lane >> 2, t = lane & 3;
    const int wm = wid >> 1, wn = wid & 1;
    const int m0 = blockIdx.y * 128, n0 = blockIdx.x * 128;

    float4 acc[2][8];
#pragma unroll
    for (int i = 0; i < 2; i++)
#pragma unroll
        for (int j = 0; j < 8; j++) acc[i][j] = make_float4(0.f,0.f,0.f,0.f);

    g_run(g_cth, g_ctl, g_wh[3], g_wl[3], gsm, m0, n0, tid, acc, wm, wn, lane);

#pragma unroll
    for (int mt = 0; mt < 2; mt++) {
        int r0 = m0 + wm * 32 + mt * 16 + g;
#pragma unroll
        for (int nt = 0; nt < 8; nt++) {
            int n = n0 + wn * 64 + nt * 8 + 2 * t;
            float bx = bias[n], by = bias[n + 1];
            float4 c = acc[mt][nt];
            *(float2*)&C[(size_t)r0 * DD + n]       = make_float2(c.x + bx, c.y + by);
            *(float2*)&C[(size_t)(r0 + 8) * DD + n] = make_float2(c.z + bx, c.w + by);
        }
    }
}

// ============================================================
// Attention: 256 thr, q-tile 128, key-tile 64, bf16 planes.
// K/V double-buffered; P packed in registers (no smem round-trip).
// ============================================================
#define ARS 144
#define AQPL 18432u   // 128*144
#define AKPL 9216u    // 64*144
#define AK_OFF 36864u
#define ABUF 18432u   // one K/V buffer (hi+lo)
#define ASMEM 73728   // Q(2 planes) + 2 KV buffers

__device__ __forceinline__ void a_issueKV(u32 bufBase, const u16* __restrict__ gh,
                                          const u16* __restrict__ gl, int row0, int tid){
#pragma unroll
    for (int i = 0; i < 4; i++) {
        int p = i >> 1;
        int rem = tid + (i & 1) * 256;
        int r = rem >> 3, c = rem & 7;
        u32 sa = bufBase + (u32)p * AKPL + (u32)(r * ARS + c * 16);
        const u16* g = p ? gl : gh;
        cpa16(sa, g + (size_t)(row0 + r) * HD + c * 8);
    }
}

__global__ __launch_bounds__(256, 2) void attn_mma(void)
{
    extern __shared__ char sm[];
    u32 sb = smem_u32(sm);

    const int tid = threadIdx.x, lane = tid & 31, wid = tid >> 5;
    const int g = lane >> 2, t = lane & 3;
    const int qt = 15 - blockIdx.x;
    const int h = blockIdx.y, b = blockIdx.z;
    const int q0 = qt * 128, ktmax = 2 * qt + 1;
    const size_t ho = (size_t)(b * HH + h) * NN * HD;
    const u16 *Qh = g_qh + ho, *Ql = g_ql + ho;
    const u16 *Kh = g_kh + ho, *Kl = g_kl + ho;
    const u16 *Vh = g_vh + ho, *Vl = g_vl + ho;
    float* Sc = g_s + (size_t)((b * HH + h) * 16 + qt) * 262144 + wid * 1024 + lane * 2;

    const int wr = wid * 16;
    const int gr0 = q0 + wr + g, gr1 = gr0 + 8;

    const u32 qBase = sb + (u32)((wr + (lane & 7) + 8 * ((lane >> 3) & 1)) * ARS + 16 * (lane >> 4));
    const u32 kOff = (u32)(((lane & 7) + 8 * ((lane >> 4) & 1)) * ARS + 16 * ((lane >> 3) & 1));
    const u32 vOff = (u32)(((lane & 7) + 8 * ((lane >> 3) & 1)) * ARS + 16 * (lane >> 4));

    // Q tile + K tile 0
#pragma unroll
    for (int i = 0; i < 8; i++) {
        int p = i >> 2;
        int rem = tid + (i & 3) * 256;
        int r = rem >> 3, c = rem & 7;
        u32 sa = sb + (u32)p * AQPL + (u32)(r * ARS + c * 16);
        const u16* gq = p ? Ql : Qh;
        cpa16(sa, gq + (size_t)(q0 + r) * HD + c * 8);
    }
    a_issueKV(sb + AK_OFF, Kh, Kl, 0, tid);
    cpa_commit();

    float mr[2] = {-1e30f, -1e30f}, lr[2] = {0.f, 0.f}, tr[2] = {0.f, 0.f};

    // ================= pass A =================
    for (int kt = 0; kt <= ktmax; kt++) {
        int ktb = kt * 64;
        bool act = (ktb <= q0 + wr + 15);
        cpa_wait0();
        __syncthreads();
        if (kt < ktmax) {
            a_issueKV(sb + AK_OFF + (u32)((kt + 1) & 1) * ABUF, Kh, Kl, ktb + 64, tid);
            cpa_commit();
        }
        if (act) {
            u32 kb = sb + AK_OFF + (u32)(kt & 1) * ABUF + kOff;
            float4 s[8];
#pragma unroll
            for (int nt = 0; nt < 8; nt++) s[nt] = make_float4(0.f,0.f,0.f,0.f);
#pragma unroll
            for (int kk = 0; kk < 4; kk++) {
                u32 qh4[4], ql4[4];
                ldmx4(qh4, qBase + (u32)(kk * 32));
                ldmx4(ql4, qBase + AQPL + (u32)(kk * 32));
#pragma unroll
                for (int ntp = 0; ntp < 4; ntp++) {
                    u32 bh4[4], bl4[4];
                    ldmx4(bh4, kb + (u32)(ntp * 2304 + kk * 32));
                    ldmx4(bl4, kb + AKPL + (u32)(ntp * 2304 + kk * 32));
                    mma3b(s[ntp*2+0], qh4, ql4, bh4, bl4, 0);
                    mma3b(s[ntp*2+1], qh4, ql4, bh4, bl4, 1);
                }
            }
            float* sp = Sc + kt * 8192;
#pragma unroll
            for (int rr = 0; rr < 2; rr++) {
                int gr = rr ? gr1 : gr0;
                float sv[16], cm = -1e30f;
#pragma unroll
                for (int nt = 0; nt < 8; nt++) {
                    float x0 = rr ? s[nt].z : s[nt].x;
                    float x1 = rr ? s[nt].w : s[nt].y;
                    int gc = ktb + nt * 8 + 2 * t;
                    sv[2*nt]   = (gc     <= gr) ? x0 * 0.125f : -1e30f;
                    sv[2*nt+1] = (gc + 1 <= gr) ? x1 * 0.125f : -1e30f;
                    cm = fmaxf(cm, fmaxf(sv[2*nt], sv[2*nt+1]));
                    *(float2*)&sp[(rr * 8 + nt) * 64] = make_float2(sv[2*nt], sv[2*nt+1]);
                }
                cm = fmaxf(cm, __shfl_xor_sync(0xffffffffu, cm, 1));
                cm = fmaxf(cm, __shfl_xor_sync(0xffffffffu, cm, 2));
                if (cm > -1e29f) {
                    float mn = fmaxf(mr[rr], cm), se = 0.f, st = 0.f;
#pragma unroll
                    for (int i = 0; i < 16; i++) {
                        float e = __expf(sv[i] - mn);
                        se += e; st = fmaf(e, sv[i], st);
                    }
                    se += __shfl_xor_sync(0xffffffffu, se, 1);
                    se += __shfl_xor_sync(0xffffffffu, se, 2);
                    st += __shfl_xor_sync(0xffffffffu, st, 1);
                    st += __shfl_xor_sync(0xffffffffu, st, 2);
                    float corr = __expf(mr[rr] - mn);
                    lr[rr] = fmaf(lr[rr], corr, se);
                    tr[rr] = fmaf(tr[rr], corr, st);
                    mr[rr] = mn;
                }
            }
        }
    }

    float bsc[2], bm[2], l2[2] = {0.f, 0.f};
#pragma unroll
    for (int rr = 0; rr < 2; rr++) {
        float ent = logf(lr[rr]) + mr[rr] - tr[rr] / lr[rr];
        float beta = 1.f;
        if (ent > 0.5f) {
            float poly = ((((-0.037f * ent + 0.481f) * ent - 2.3f) * ent + 4.917f) * ent - 1.791f);
            beta = fmaxf(poly, 1.f);
        }
        bsc[rr] = beta;
        bm[rr] = beta * mr[rr];
    }

    float4 o[8];
#pragma unroll
    for (int nt = 0; nt < 8; nt++) o[nt] = make_float4(0.f,0.f,0.f,0.f);

    __syncthreads();                       // pass A reads done before V0 overwrite
    a_issueKV(sb + AK_OFF, Vh, Vl, 0, tid);
    cpa_commit();

    // ================= pass B =================
    for (int kt = 0; kt <= ktmax; kt++) {
        int ktb = kt * 64;
        bool act = (ktb <= q0 + wr + 15);
        cpa_wait0();
        __syncthreads();
        if (kt < ktmax) {
            a_issueKV(sb + AK_OFF + (u32)((kt + 1) & 1) * ABUF, Vh, Vl, ktb + 64, tid);
            cpa_commit();
        }
        if (act) {
            u32 vb = sb + AK_OFF + (u32)(kt & 1) * ABUF + vOff;
            const float* sp = Sc + kt * 8192;
#pragma unroll
            for (int kk = 0; kk < 4; kk++) {
                u32 ah4[4], al4[4];
#pragma unroll
                for (int half = 0; half < 2; half++) {
                    int nt = 2 * kk + half;
#pragma unroll
                    for (int rr = 0; rr < 2; rr++) {
                        float2 sv2 = *(const float2*)&sp[(rr * 8 + nt) * 64];
                        float p0 = __expf(fmaf(bsc[rr], sv2.x, -bm[rr]));
                        float p1 = __expf(fmaf(bsc[rr], sv2.y, -bm[rr]));
                        l2[rr] += p0 + p1;
                        u32 hi = packbf(p0, p1);
                        float f0 = __uint_as_float(hi << 16);
                        float f1 = __uint_as_float(hi & 0xffff0000u);
                        u32 lo = packbf(p0 - f0, p1 - f1);
                        ah4[half * 2 + rr] = hi;
                        al4[half * 2 + rr] = lo;
                    }
                }
#pragma unroll
                for (int ntp = 0; ntp < 4; ntp++) {
                    u32 vh4[4], vl4[4];
                    ldmx4t(vh4, vb + (u32)(kk * 2304 + ntp * 32));
                    ldmx4t(vl4, vb + AKPL + (u32)(kk * 2304 + ntp * 32));
                    mma3b(o[ntp*2+0], ah4, al4, vh4, vl4, 0);
                    mma3b(o[ntp*2+1], ah4, al4, vh4, vl4, 1);
                }
            }
        }
    }

#pragma unroll
    for (int rr = 0; rr < 2; rr++) {
        l2[rr] += __shfl_xor_sync(0xffffffffu, l2[rr], 1);
        l2[rr] += __shfl_xor_sync(0xffffffffu, l2[rr], 2);
    }
    float inv0 = 1.f / l2[0], inv1 = 1.f / l2[1];
    size_t row0 = ((size_t)(b * NN) + gr0) * DD + h * HD;
    size_t row1 = ((size_t)(b * NN) + gr1) * DD + h * HD;
#pragma unroll
    for (int nt = 0; nt < 8; nt++) {
        int c = nt * 8 + 2 * t;
        u16 h0,l0h,h1,l1h;
        bsplit(o[nt].x * inv0, h0, l0h); bsplit(o[nt].y * inv0, h1, l1h);
        *(ushort2*)&g_cth[row0 + c] = make_ushort2(h0,h1);
        *(ushort2*)&g_ctl[row0 + c] = make_ushort2(l0h,l1h);
        bsplit(o[nt].z * inv1, h0, l0h); bsplit(o[nt].w * inv1, h1, l1h);
        *(ushort2*)&g_cth[row1 + c] = make_ushort2(h0,h1);
        *(ushort2*)&g_ctl[row1 + c] = make_ushort2(l0h,l1h);
    }
}

// ============================================================
extern "C" void kernel_launch(void* const* d_in, const int* in_sizes, int n_in,
                              void* d_out, int out_size)
{
    const float* x  = (const float*)d_in[0];
    const float* Wq = (const float*)d_in[1];
    const float* Wk = (const float*)d_in[2];
    const float* Wv = (const float*)d_in[3];
    const float* Wo = (const float*)d_in[4];
    const float* bo = (const float*)d_in[5];
    float* out = (float*)d_out;

    const int gsmem = 2 * GSTG;
    cudaFuncSetAttribute(gemm_qkv, cudaFuncAttributeMaxDynamicSharedMemorySize, gsmem);
    cudaFuncSetAttribute(gemm_out, cudaFuncAttributeMaxDynamicSharedMemorySize, gsmem);
    cudaFuncSetAttribute(attn_mma, cudaFuncAttributeMaxDynamicSharedMemorySize, ASMEM);

    presplitX<<<4096, 256>>>((const float4*)x);
    dim3 wg(1024, 4);
    presplitW<<<wg, 256>>>((const float4*)Wq, (const float4*)Wk,
                           (const float4*)Wv, (const float4*)Wo);

    dim3 qg(24, 32);
    gemm_qkv<<<qg, 256, gsmem>>>();

    dim3 ag(NN / 128, HH, BB);
    attn_mma<<<ag, 256, ASMEM>>>();

    dim3 og(8, 32);
    gemm_out<<<og, 256, gsmem>>>(bo, out);
}

// round 9
// speedup vs baseline: 2.9546x; 1.1930x over previous
#include <cuda_runtime.h>
#include <cstdint>

#define BB 2
#define NN 2048
#define DD 1024
#define HH 16
#define HD 64
typedef unsigned short u16;
typedef uint32_t u32;

__device__ __align__(16) u16 g_xh[(size_t)BB*NN*DD];
__device__ __align__(16) u16 g_xl[(size_t)BB*NN*DD];
__device__ __align__(16) u16 g_wh[4][(size_t)DD*DD];
__device__ __align__(16) u16 g_wl[4][(size_t)DD*DD];
__device__ __align__(16) u16 g_qh[(size_t)BB*HH*NN*HD];
__device__ __align__(16) u16 g_ql[(size_t)BB*HH*NN*HD];
__device__ __align__(16) u16 g_kh[(size_t)BB*HH*NN*HD];
__device__ __align__(16) u16 g_kl[(size_t)BB*HH*NN*HD];
__device__ __align__(16) u16 g_vh[(size_t)BB*HH*NN*HD];
__device__ __align__(16) u16 g_vl[(size_t)BB*HH*NN*HD];
__device__ __align__(16) u16 g_cth[(size_t)BB*NN*DD];
__device__ __align__(16) u16 g_ctl[(size_t)BB*NN*DD];
__device__ float g_s[(size_t)512*262144];

__device__ __forceinline__ void bsplit(float x, u16 &h, u16 &l){
    asm("cvt.rn.bf16.f32 %0, %1;" : "=h"(h) : "f"(x));
    float hf = __uint_as_float((u32)h << 16);
    asm("cvt.rn.bf16.f32 %0, %1;" : "=h"(l) : "f"(x - hf));
}
__device__ __forceinline__ u32 packbf(float lo, float hi){
    u32 r; asm("cvt.rn.bf16x2.f32 %0, %1, %2;" : "=r"(r) : "f"(hi), "f"(lo));
    return r;
}
__device__ __forceinline__ float ex2f(float x){
    float r; asm("ex2.approx.ftz.f32 %0, %1;" : "=f"(r) : "f"(x));
    return r;
}
__device__ __forceinline__ float lg2f(float x){
    float r; asm("lg2.approx.ftz.f32 %0, %1;" : "=f"(r) : "f"(x));
    return r;
}
__device__ __forceinline__ u32 smem_u32(const void* p){
    u32 a;
    asm("{ .reg .u64 t; cvta.to.shared.u64 t, %1; cvt.u32.u64 %0, t; }" : "=r"(a) : "l"(p));
    return a;
}
__device__ __forceinline__ void cpa16(u32 dst, const void* src){
    asm volatile("cp.async.cg.shared.global [%0], [%1], 16;" :: "r"(dst), "l"(src));
}
__device__ __forceinline__ void cpa_commit(){ asm volatile("cp.async.commit_group;" ::: "memory"); }
__device__ __forceinline__ void cpa_wait0(){ asm volatile("cp.async.wait_group 0;" ::: "memory"); }

__device__ __forceinline__ void ldmx4(u32* r, u32 a){
    asm volatile("ldmatrix.sync.aligned.m8n8.x4.shared.b16 {%0,%1,%2,%3}, [%4];"
        : "=r"(r[0]), "=r"(r[1]), "=r"(r[2]), "=r"(r[3]) : "r"(a));
}
__device__ __forceinline__ void ldmx4t(u32* r, u32 a){
    asm volatile("ldmatrix.sync.aligned.m8n8.x4.trans.shared.b16 {%0,%1,%2,%3}, [%4];"
        : "=r"(r[0]), "=r"(r[1]), "=r"(r[2]), "=r"(r[3]) : "r"(a));
}
__device__ __forceinline__ void mmab(float4& d, const u32* a, u32 b0, u32 b1){
    asm volatile("mma.sync.aligned.m16n8k16.row.col.f32.bf16.bf16.f32 "
        "{%0,%1,%2,%3},{%4,%5,%6,%7},{%8,%9},{%0,%1,%2,%3};"
        : "+f"(d.x), "+f"(d.y), "+f"(d.z), "+f"(d.w)
        : "r"(a[0]), "r"(a[1]), "r"(a[2]), "r"(a[3]), "r"(b0), "r"(b1));
}
__device__ __forceinline__ void mma3b(float4& d, const u32* ah, const u32* al,
                                      const u32* bh, const u32* bl, int ng){
    mmab(d, ah, bh[2*ng], bh[2*ng+1]);
    mmab(d, ah, bl[2*ng], bl[2*ng+1]);
    mmab(d, al, bh[2*ng], bh[2*ng+1]);
}

// ============================================================
// presplit
// ============================================================
__device__ __forceinline__ void dosplit4(const float4* src, ushort4* hi, ushort4* lo, int i){
    float4 v = src[i];
    u16 h0,l0,h1,l1,h2,l2,h3,l3;
    bsplit(v.x,h0,l0); bsplit(v.y,h1,l1); bsplit(v.z,h2,l2); bsplit(v.w,h3,l3);
    hi[i] = make_ushort4(h0,h1,h2,h3);
    lo[i] = make_ushort4(l0,l1,l2,l3);
}
__global__ __launch_bounds__(256) void presplitX(const float4* __restrict__ x){
    int i = blockIdx.x * 256 + threadIdx.x;
    dosplit4(x, (ushort4*)g_xh, (ushort4*)g_xl, i);
}
__global__ __launch_bounds__(256) void presplitW(const float4* __restrict__ Wq,
                                                 const float4* __restrict__ Wk,
                                                 const float4* __restrict__ Wv,
                                                 const float4* __restrict__ Wo){
    int m = blockIdx.y;
    const float4* src = (m == 0) ? Wq : (m == 1) ? Wk : (m == 2) ? Wv : Wo;
    int i = blockIdx.x * 256 + threadIdx.x;
    dosplit4(src, (ushort4*)g_wh[m], (ushort4*)g_wl[m], i);
}

// ============================================================
// GEMM core: 128x128 tile, BK=32, 2-stage cp.async, ONE sync/iter.
// ============================================================
#define GRS 80
#define GPL 10240
#define GSTG 40960

__device__ __forceinline__ void g_issue(u32 sb_stage,
        const u16* __restrict__ Ah, const u16* __restrict__ Al,
        const u16* __restrict__ Bh, const u16* __restrict__ Bl,
        int m0, int n0, int k0, int tid){
#pragma unroll
    for (int i = 0; i < 8; i++) {
        int p = i >> 1;
        int rem = tid + (i & 1) * 256;
        int r = rem >> 2, c = rem & 3;
        u32 sa = sb_stage + (u32)p * GPL + (u32)(r * GRS + c * 16);
        const u16* g = (p == 0) ? Ah : (p == 1) ? Al : (p == 2) ? Bh : Bl;
        int rb = (p < 2) ? m0 : n0;
        cpa16(sa, g + (size_t)(rb + r) * DD + k0 + c * 8);
    }
}

__device__ __forceinline__ void g_run(const u16* Ah, const u16* Al, const u16* Bh, const u16* Bl,
                                      char* sm, int m0, int n0, int tid,
                                      float4 (&acc)[2][8], int wm, int wn, int lane){
    u32 sb = smem_u32(sm);
    u32 aBase = sb + (u32)((wm * 32 + (lane & 7) + 8 * ((lane >> 3) & 1)) * GRS + 16 * (lane >> 4));
    u32 bBase = sb + 20480u + (u32)((wn * 64 + (lane & 7) + 8 * ((lane >> 4) & 1)) * GRS + 16 * ((lane >> 3) & 1));

    g_issue(sb, Ah, Al, Bh, Bl, m0, n0, 0, tid);
    cpa_commit();
    for (int k0 = 0; k0 < DD; k0 += 32) {
        u32 so = ((k0 >> 5) & 1) ? GSTG : 0u;
        cpa_wait0();
        __syncthreads();
        if (k0 + 32 < DD) {
            g_issue(sb + (so ^ GSTG), Ah, Al, Bh, Bl, m0, n0, k0 + 32, tid);
            cpa_commit();
        }
#pragma unroll
        for (int kk = 0; kk < 2; kk++) {
            u32 ah4[2][4], al4[2][4];
#pragma unroll
            for (int mt = 0; mt < 2; mt++) {
                ldmx4(ah4[mt], aBase + so + (u32)(mt * 1280 + kk * 32));
                ldmx4(al4[mt], aBase + so + GPL + (u32)(mt * 1280 + kk * 32));
            }
#pragma unroll
            for (int ntp = 0; ntp < 4; ntp++) {
                u32 bh4[4], bl4[4];
                ldmx4(bh4, bBase + so + (u32)(ntp * 1280 + kk * 32));
                ldmx4(bl4, bBase + so + GPL + (u32)(ntp * 1280 + kk * 32));
#pragma unroll
                for (int mt = 0; mt < 2; mt++) {
                    mma3b(acc[mt][ntp*2+0], ah4[mt], al4[mt], bh4, bl4, 0);
                    mma3b(acc[mt][ntp*2+1], ah4[mt], al4[mt], bh4, bl4, 1);
                }
            }
        }
    }
}

__global__ __launch_bounds__(256, 2) void gemm_qkv(void)
{
    extern __shared__ char gsm[];
    const int tid = threadIdx.x, lane = tid & 31, wid = tid >> 5;
    const int g = lane >> 2, t = lane & 3;
    const int wm = wid >> 1, wn = wid & 1;
    const int mat = blockIdx.x >> 3;
    const int m0 = blockIdx.y * 128, n0 = (blockIdx.x & 7) * 128;
    const u16 *Bh = g_wh[mat], *Bl = g_wl[mat];
    u16 *Ch, *Cl;
    if (mat == 0) { Ch = g_qh; Cl = g_ql; }
    else if (mat == 1) { Ch = g_kh; Cl = g_kl; }
    else { Ch = g_vh; Cl = g_vl; }

    float4 acc[2][8];
#pragma unroll
    for (int i = 0; i < 2; i++)
#pragma unroll
        for (int j = 0; j < 8; j++) acc[i][j] = make_float4(0.f,0.f,0.f,0.f);

    g_run(g_xh, g_xl, Bh, Bl, gsm, m0, n0, tid, acc, wm, wn, lane);

#pragma unroll
    for (int mt = 0; mt < 2; mt++) {
        int r0 = m0 + wm * 32 + mt * 16 + g;
#pragma unroll
        for (int nt = 0; nt < 8; nt++) {
            int n = n0 + wn * 64 + nt * 8 + 2 * t;
            int h = n >> 6, cc = n & 63;
            float4 c = acc[mt][nt];
            int b0r = r0 >> 11, i0r = r0 & (NN - 1);
            int b1r = (r0 + 8) >> 11, i1r = (r0 + 8) & (NN - 1);
            size_t i0 = ((size_t)(b0r * HH + h) * NN + i0r) * HD + cc;
            size_t i1 = ((size_t)(b1r * HH + h) * NN + i1r) * HD + cc;
            u16 h0,l0,h1,l1;
            bsplit(c.x,h0,l0); bsplit(c.y,h1,l1);
            *(ushort2*)&Ch[i0] = make_ushort2(h0,h1);
            *(ushort2*)&Cl[i0] = make_ushort2(l0,l1);
            bsplit(c.z,h0,l0); bsplit(c.w,h1,l1);
            *(ushort2*)&Ch[i1] = make_ushort2(h0,h1);
            *(ushort2*)&Cl[i1] = make_ushort2(l0,l1);
        }
    }
}

__global__ __launch_bounds__(256, 2) void gemm_out(const float* __restrict__ bias,
                                                   float* __restrict__ C)
{
    extern __shared__ char gsm[];
    const int tid = threadIdx.x, lane = tid & 31, wid = tid >> 5;
    const int g = lane >> 2, t = lane & 3;
    const int wm = wid >> 1, wn = wid & 1;
    const int m0 = blockIdx.y * 128, n0 = blockIdx.x * 128;

    float4 acc[2][8];
#pragma unroll
    for (int i = 0; i < 2; i++)
#pragma unroll
        for (int j = 0; j < 8; j++) acc[i][j] = make_float4(0.f,0.f,0.f,0.f);

    g_run(g_cth, g_ctl, g_wh[3], g_wl[3], gsm, m0, n0, tid, acc, wm, wn, lane);

#pragma unroll
    for (int mt = 0; mt < 2; mt++) {
        int r0 = m0 + wm * 32 + mt * 16 + g;
#pragma unroll
        for (int nt = 0; nt < 8; nt++) {
            int n = n0 + wn * 64 + nt * 8 + 2 * t;
            float bx = bias[n], by = bias[n + 1];
            float4 c = acc[mt][nt];
            *(float2*)&C[(size_t)r0 * DD + n]       = make_float2(c.x + bx, c.y + by);
            *(float2*)&C[(size_t)(r0 + 8) * DD + n] = make_float2(c.z + bx, c.w + by);
        }
    }
}

// ============================================================
// Attention: log2-domain softmax, S cached in log2 units.
// ============================================================
#define ARS 144
#define AQPL 18432u
#define AKPL 9216u
#define AK_OFF 36864u
#define ABUF 18432u
#define ASMEM 73728
#define SCL 0.180336880f   // 0.125 * log2(e)
#define LN2 0.693147181f

__device__ __forceinline__ void a_issueKV(u32 bufBase, const u16* __restrict__ gh,
                                          const u16* __restrict__ gl, int row0, int tid){
#pragma unroll
    for (int i = 0; i < 4; i++) {
        int p = i >> 1;
        int rem = tid + (i & 1) * 256;
        int r = rem >> 3, c = rem & 7;
        u32 sa = bufBase + (u32)p * AKPL + (u32)(r * ARS + c * 16);
        const u16* g = p ? gl : gh;
        cpa16(sa, g + (size_t)(row0 + r) * HD + c * 8);
    }
}

__global__ __launch_bounds__(256, 2) void attn_mma(void)
{
    extern __shared__ char sm[];
    u32 sb = smem_u32(sm);

    const int tid = threadIdx.x, lane = tid & 31, wid = tid >> 5;
    const int g = lane >> 2, t = lane & 3;
    // qt-major descending: all biggest tiles launch first
    const int qt = 15 - (int)(blockIdx.x >> 5);
    const int bh = blockIdx.x & 31;
    const int h = bh >> 1, b = bh & 1;
    const int q0 = qt * 128, ktmax = 2 * qt + 1;
    const size_t ho = (size_t)(b * HH + h) * NN * HD;
    const u16 *Qh = g_qh + ho, *Ql = g_ql + ho;
    const u16 *Kh = g_kh + ho, *Kl = g_kl + ho;
    const u16 *Vh = g_vh + ho, *Vl = g_vl + ho;
    float* Sc = g_s + (size_t)((b * HH + h) * 16 + qt) * 262144 + wid * 1024 + lane * 2;

    const int wr = wid * 16;
    const int gr0 = q0 + wr + g, gr1 = gr0 + 8;

    const u32 qBase = sb + (u32)((wr + (lane & 7) + 8 * ((lane >> 3) & 1)) * ARS + 16 * (lane >> 4));
    const u32 kOff = (u32)(((lane & 7) + 8 * ((lane >> 4) & 1)) * ARS + 16 * ((lane >> 3) & 1));
    const u32 vOff = (u32)(((lane & 7) + 8 * ((lane >> 3) & 1)) * ARS + 16 * (lane >> 4));

#pragma unroll
    for (int i = 0; i < 8; i++) {
        int p = i >> 2;
        int rem = tid + (i & 3) * 256;
        int r = rem >> 3, c = rem & 7;
        u32 sa = sb + (u32)p * AQPL + (u32)(r * ARS + c * 16);
        const u16* gq = p ? Ql : Qh;
        cpa16(sa, gq + (size_t)(q0 + r) * HD + c * 8);
    }
    a_issueKV(sb + AK_OFF, Kh, Kl, 0, tid);
    cpa_commit();

    float mr[2] = {-1e30f, -1e30f}, lr[2] = {0.f, 0.f}, tr[2] = {0.f, 0.f};

    // ================= pass A (log2 domain) =================
    for (int kt = 0; kt <= ktmax; kt++) {
        int ktb = kt * 64;
        bool act = (ktb <= q0 + wr + 15);
        cpa_wait0();
        __syncthreads();
        if (kt < ktmax) {
            a_issueKV(sb + AK_OFF + (u32)((kt + 1) & 1) * ABUF, Kh, Kl, ktb + 64, tid);
            cpa_commit();
        }
        if (act) {
            u32 kb = sb + AK_OFF + (u32)(kt & 1) * ABUF + kOff;
            float4 s[8];
#pragma unroll
            for (int nt = 0; nt < 8; nt++) s[nt] = make_float4(0.f,0.f,0.f,0.f);
#pragma unroll
            for (int kk = 0; kk < 4; kk++) {
                u32 qh4[4], ql4[4];
                ldmx4(qh4, qBase + (u32)(kk * 32));
                ldmx4(ql4, qBase + AQPL + (u32)(kk * 32));
#pragma unroll
                for (int ntp = 0; ntp < 4; ntp++) {
                    u32 bh4[4], bl4[4];
                    ldmx4(bh4, kb + (u32)(ntp * 2304 + kk * 32));
                    ldmx4(bl4, kb + AKPL + (u32)(ntp * 2304 + kk * 32));
                    mma3b(s[ntp*2+0], qh4, ql4, bh4, bl4, 0);
                    mma3b(s[ntp*2+1], qh4, ql4, bh4, bl4, 1);
                }
            }
            float* sp = Sc + kt * 8192;
#pragma unroll
            for (int rr = 0; rr < 2; rr++) {
                int gr = rr ? gr1 : gr0;
                float sv[16], cm = -1e30f;
#pragma unroll
                for (int nt = 0; nt < 8; nt++) {
                    float x0 = rr ? s[nt].z : s[nt].x;
                    float x1 = rr ? s[nt].w : s[nt].y;
                    int gc = ktb + nt * 8 + 2 * t;
                    sv[2*nt]   = (gc     <= gr) ? x0 * SCL : -1e30f;
                    sv[2*nt+1] = (gc + 1 <= gr) ? x1 * SCL : -1e30f;
                    cm = fmaxf(cm, fmaxf(sv[2*nt], sv[2*nt+1]));
                    *(float2*)&sp[(rr * 8 + nt) * 64] = make_float2(sv[2*nt], sv[2*nt+1]);
                }
                cm = fmaxf(cm, __shfl_xor_sync(0xffffffffu, cm, 1));
                cm = fmaxf(cm, __shfl_xor_sync(0xffffffffu, cm, 2));
                if (cm > -1e29f) {
                    float mn = fmaxf(mr[rr], cm), se = 0.f, st = 0.f;
#pragma unroll
                    for (int i = 0; i < 16; i++) {
                        float e = ex2f(sv[i] - mn);
                        se += e; st = fmaf(e, sv[i], st);
                    }
                    se += __shfl_xor_sync(0xffffffffu, se, 1);
                    se += __shfl_xor_sync(0xffffffffu, se, 2);
                    st += __shfl_xor_sync(0xffffffffu, st, 1);
                    st += __shfl_xor_sync(0xffffffffu, st, 2);
                    float corr = ex2f(mr[rr] - mn);
                    lr[rr] = fmaf(lr[rr], corr, se);
                    tr[rr] = fmaf(tr[rr], corr, st);
                    mr[rr] = mn;
                }
            }
        }
    }

    float bsc[2], bm[2], l2[2] = {0.f, 0.f};
#pragma unroll
    for (int rr = 0; rr < 2; rr++) {
        // entropy = ln2 * (log2(l) + m_l2 - t_l2 / l)
        float ent = LN2 * (lg2f(lr[rr]) + mr[rr] - tr[rr] / lr[rr]);
        float beta = 1.f;
        if (ent > 0.5f) {
            float poly = ((((-0.037f * ent + 0.481f) * ent - 2.3f) * ent + 4.917f) * ent - 1.791f);
            beta = fmaxf(poly, 1.f);
        }
        bsc[rr] = beta;
        bm[rr] = beta * mr[rr];
    }

    float4 o[8];
#pragma unroll
    for (int nt = 0; nt < 8; nt++) o[nt] = make_float4(0.f,0.f,0.f,0.f);

    __syncthreads();
    a_issueKV(sb + AK_OFF, Vh, Vl, 0, tid);
    cpa_commit();

    // ================= pass B =================
    for (int kt = 0; kt <= ktmax; kt++) {
        int ktb = kt * 64;
        bool act = (ktb <= q0 + wr + 15);
        cpa_wait0();
        __syncthreads();
        if (kt < ktmax) {
            a_issueKV(sb + AK_OFF + (u32)((kt + 1) & 1) * ABUF, Vh, Vl, ktb + 64, tid);
            cpa_commit();
        }
        if (act) {
            u32 vb = sb + AK_OFF + (u32)(kt & 1) * ABUF + vOff;
            const float* sp = Sc + kt * 8192;
#pragma unroll
            for (int kk = 0; kk < 4; kk++) {
                u32 ah4[4], al4[4];
#pragma unroll
                for (int half = 0; half < 2; half++) {
                    int nt = 2 * kk + half;
#pragma unroll
                    for (int rr = 0; rr < 2; rr++) {
                        float2 sv2 = *(const float2*)&sp[(rr * 8 + nt) * 64];
                        float p0 = ex2f(fmaf(bsc[rr], sv2.x, -bm[rr]));
                        float p1 = ex2f(fmaf(bsc[rr], sv2.y, -bm[rr]));
                        l2[rr] += p0 + p1;
                        u32 hi = packbf(p0, p1);
                        float f0 = __uint_as_float(hi << 16);
                        float f1 = __uint_as_float(hi & 0xffff0000u);
                        u32 lo = packbf(p0 - f0, p1 - f1);
                        ah4[half * 2 + rr] = hi;
                        al4[half * 2 + rr] = lo;
                    }
                }
#pragma unroll
                for (int ntp = 0; ntp < 4; ntp++) {
                    u32 vh4[4], vl4[4];
                    ldmx4t(vh4, vb + (u32)(kk * 2304 + ntp * 32));
                    ldmx4t(vl4, vb + AKPL + (u32)(kk * 2304 + ntp * 32));
                    mma3b(o[ntp*2+0], ah4, al4, vh4, vl4, 0);
                    mma3b(o[ntp*2+1], ah4, al4, vh4, vl4, 1);
                }
            }
        }
    }

#pragma unroll
    for (int rr = 0; rr < 2; rr++) {
        l2[rr] += __shfl_xor_sync(0xffffffffu, l2[rr], 1);
        l2[rr] += __shfl_xor_sync(0xffffffffu, l2[rr], 2);
    }
    float inv0 = 1.f / l2[0], inv1 = 1.f / l2[1];
    size_t row0 = ((size_t)(b * NN) + gr0) * DD + h * HD;
    size_t row1 = ((size_t)(b * NN) + gr1) * DD + h * HD;
#pragma unroll
    for (int nt = 0; nt < 8; nt++) {
        int c = nt * 8 + 2 * t;
        u16 h0,l0h,h1,l1h;
        bsplit(o[nt].x * inv0, h0, l0h); bsplit(o[nt].y * inv0, h1, l1h);
        *(ushort2*)&g_cth[row0 + c] = make_ushort2(h0,h1);
        *(ushort2*)&g_ctl[row0 + c] = make_ushort2(l0h,l1h);
        bsplit(o[nt].z * inv1, h0, l0h); bsplit(o[nt].w * inv1, h1, l1h);
        *(ushort2*)&g_cth[row1 + c] = make_ushort2(h0,h1);
        *(ushort2*)&g_ctl[row1 + c] = make_ushort2(l0h,l1h);
    }
}

// ============================================================
extern "C" void kernel_launch(void* const* d_in, const int* in_sizes, int n_in,
                              void* d_out, int out_size)
{
    const float* x  = (const float*)d_in[0];
    const float* Wq = (const float*)d_in[1];
    const float* Wk = (const float*)d_in[2];
    const float* Wv = (const float*)d_in[3];
    const float* Wo = (const float*)d_in[4];
    const float* bo = (const float*)d_in[5];
    float* out = (float*)d_out;

    const int gsmem = 2 * GSTG;
    cudaFuncSetAttribute(gemm_qkv, cudaFuncAttributeMaxDynamicSharedMemorySize, gsmem);
    cudaFuncSetAttribute(gemm_out, cudaFuncAttributeMaxDynamicSharedMemorySize, gsmem);
    cudaFuncSetAttribute(attn_mma, cudaFuncAttributeMaxDynamicSharedMemorySize, ASMEM);

    presplitX<<<4096, 256>>>((const float4*)x);
    dim3 wg(1024, 4);
    presplitW<<<wg, 256>>>((const float4*)Wq, (const float4*)Wk,
                           (const float4*)Wv, (const float4*)Wo);

    dim3 qg(24, 32);
    gemm_qkv<<<qg, 256, gsmem>>>();

    attn_mma<<<512, 256, ASMEM>>>();

    dim3 og(8, 32);
    gemm_out<<<og, 256, gsmem>>>(bo, out);
}